// round 5
// baseline (speedup 1.0000x reference)
#include <cuda_runtime.h>
#include <cuda_bf16.h>
#include <cuda_fp16.h>
#include <cstdint>
#include <math.h>

#define NN 8192
#define FD 256
#define ALPHA_S 0.2f

// ---------------- device global scratch ----------------
__device__ __nv_bfloat16 g_hhi[NN * FD];
__device__ __nv_bfloat16 g_hlo[NN * FD];
__device__ __nv_bfloat16 g_WThi[FD * FD];
__device__ __nv_bfloat16 g_WTlo[FD * FD];
__device__ __half g_WhThi[FD * NN];   // Wh^T [n][k] fp16 hi/lo
__device__ __half g_WhTlo[FD * NN];
__device__ float g_f1[NN];
__device__ float g_f2[NN];
__device__ float g_f2max;

// ---------------- PTX helpers ----------------
__device__ __forceinline__ uint32_t smem_u32(const void* p) {
    uint32_t a;
    asm("{ .reg .u64 t; cvta.to.shared.u64 t, %1; cvt.u32.u64 %0, t; }"
        : "=r"(a) : "l"(p));
    return a;
}
__device__ __forceinline__ void cp_async16(uint32_t dst, const void* src) {
    asm volatile("cp.async.cg.shared.global [%0], [%1], 16;"
                 :: "r"(dst), "l"(src) : "memory");
}
__device__ __forceinline__ void cp_commit() {
    asm volatile("cp.async.commit_group;" ::: "memory");
}
template<int N>
__device__ __forceinline__ void cp_wait() {
    asm volatile("cp.async.wait_group %0;" :: "n"(N) : "memory");
}
__device__ __forceinline__ void ldm_x4(uint32_t addr, uint32_t& r0, uint32_t& r1,
                                       uint32_t& r2, uint32_t& r3) {
    asm volatile("ldmatrix.sync.aligned.m8n8.x4.shared.b16 {%0,%1,%2,%3}, [%4];"
                 : "=r"(r0), "=r"(r1), "=r"(r2), "=r"(r3) : "r"(addr));
}
__device__ __forceinline__ void mma_bf16(float* c, const uint32_t* a, const uint32_t* b) {
    asm volatile(
        "mma.sync.aligned.m16n8k16.row.col.f32.bf16.bf16.f32 "
        "{%0,%1,%2,%3}, {%4,%5,%6,%7}, {%8,%9}, {%0,%1,%2,%3};"
        : "+f"(c[0]), "+f"(c[1]), "+f"(c[2]), "+f"(c[3])
        : "r"(a[0]), "r"(a[1]), "r"(a[2]), "r"(a[3]), "r"(b[0]), "r"(b[1]));
}
__device__ __forceinline__ void mma_fp16(float* c, const uint32_t* a, const uint32_t* b) {
    asm volatile(
        "mma.sync.aligned.m16n8k16.row.col.f32.f16.f16.f32 "
        "{%0,%1,%2,%3}, {%4,%5,%6,%7}, {%8,%9}, {%0,%1,%2,%3};"
        : "+f"(c[0]), "+f"(c[1]), "+f"(c[2]), "+f"(c[3])
        : "r"(a[0]), "r"(a[1]), "r"(a[2]), "r"(a[3]), "r"(b[0]), "r"(b[1]));
}

// ======================= GEMM1: Wh = h @ W (bf16 3-pass, high accuracy) ====
static constexpr int ROWB    = 80;
static constexpr int TILE_B  = 128 * ROWB;
static constexpr int STAGE_B = 4 * TILE_B;
static constexpr int SMEM1_SZ = 2 * STAGE_B;      // 81920

template<int KCHUNKS>
__global__ void __launch_bounds__(256, 1) mma_gemm1(
    const __nv_bfloat16* __restrict__ Ahi, const __nv_bfloat16* __restrict__ Alo,
    const __nv_bfloat16* __restrict__ Bhi, const __nv_bfloat16* __restrict__ Blo,
    __half* __restrict__ ThiOut, __half* __restrict__ TloOut)
{
    constexpr int K = KCHUNKS * 32;
    extern __shared__ char smem[];
    const uint32_t sb = smem_u32(smem);

    const int tid  = threadIdx.x;
    const int warp = tid >> 5;
    const int lane = tid & 31;
    const int wm   = warp & 3;
    const int wn   = warp >> 2;
    const int row0 = blockIdx.x * 128;
    const int col0 = blockIdx.y * 128;

    const int a_row = lane & 15;
    const int a_kb  = (lane >> 4) * 16;
    const int b_row = ((lane >> 4) << 3) + (lane & 7);
    const int b_kb  = ((lane >> 3) & 1) * 16;
    const int lrow = tid >> 2;
    const int lch  = tid & 3;

    float acc[2][8][4];
    #pragma unroll
    for (int i = 0; i < 2; i++)
        #pragma unroll
        for (int j = 0; j < 8; j++)
            #pragma unroll
            for (int q = 0; q < 4; q++) acc[i][j][q] = 0.0f;

    auto load_stage = [&](int s, int kc) {
        const uint32_t base = sb + s * STAGE_B;
        const int k0 = kc * 32;
        #pragma unroll
        for (int it = 0; it < 2; it++) {
            int r = lrow + it * 64;
            uint32_t doff = r * ROWB + lch * 16;
            size_t ga = (size_t)(row0 + r) * K + k0 + lch * 8;
            size_t gb = (size_t)(col0 + r) * K + k0 + lch * 8;
            cp_async16(base + 0 * TILE_B + doff, Ahi + ga);
            cp_async16(base + 1 * TILE_B + doff, Alo + ga);
            cp_async16(base + 2 * TILE_B + doff, Bhi + gb);
            cp_async16(base + 3 * TILE_B + doff, Blo + gb);
        }
        cp_commit();
    };

    load_stage(0, 0);

    for (int c = 0; c < KCHUNKS; c++) {
        const int s = c & 1;
        if (c + 1 < KCHUNKS) { load_stage(s ^ 1, c + 1); cp_wait<1>(); }
        else                 { cp_wait<0>(); }
        __syncthreads();

        const uint32_t base = sb + s * STAGE_B;
        #pragma unroll
        for (int ks = 0; ks < 2; ks++) {
            const int kb = ks * 32;
            uint32_t ah[2][4], al[2][4], bh[16], bl[16];
            #pragma unroll
            for (int mt = 0; mt < 2; mt++) {
                uint32_t ra = (wm * 32 + mt * 16 + a_row) * ROWB + kb + a_kb;
                ldm_x4(base + 0 * TILE_B + ra, ah[mt][0], ah[mt][1], ah[mt][2], ah[mt][3]);
                ldm_x4(base + 1 * TILE_B + ra, al[mt][0], al[mt][1], al[mt][2], al[mt][3]);
            }
            #pragma unroll
            for (int nb = 0; nb < 4; nb++) {
                uint32_t rb = (wn * 64 + nb * 16 + b_row) * ROWB + kb + b_kb;
                ldm_x4(base + 2 * TILE_B + rb, bh[4*nb], bh[4*nb+1], bh[4*nb+2], bh[4*nb+3]);
                ldm_x4(base + 3 * TILE_B + rb, bl[4*nb], bl[4*nb+1], bl[4*nb+2], bl[4*nb+3]);
            }
            #pragma unroll
            for (int mt = 0; mt < 2; mt++)
                #pragma unroll
                for (int nt = 0; nt < 8; nt++) {
                    mma_bf16(acc[mt][nt], ah[mt], bh + 2*nt);
                    mma_bf16(acc[mt][nt], ah[mt], bl + 2*nt);
                    mma_bf16(acc[mt][nt], al[mt], bh + 2*nt);
                }
        }
        __syncthreads();
    }

    // stage C^T fp16 hi/lo through smem, then coalesced store to [n][m]
    constexpr int TST = 272;
    __half* shT = (__half*)smem;
    __half* slT = (__half*)(smem + 128 * TST);
    #pragma unroll
    for (int mt = 0; mt < 2; mt++) {
        #pragma unroll
        for (int nt = 0; nt < 8; nt++) {
            int ml = wm * 32 + mt * 16 + (lane >> 2);
            int nl = wn * 64 + nt * 8 + (lane & 3) * 2;
            #pragma unroll
            for (int q = 0; q < 4; q++) {
                int m = ml + (q >> 1) * 8;
                int n = nl + (q & 1);
                float v = acc[mt][nt][q];
                __half hb = __float2half_rn(v);
                __half lb = __float2half_rn(v - __half2float(hb));
                shT[n * 136 + m] = hb;
                slT[n * 136 + m] = lb;
            }
        }
    }
    __syncthreads();
    #pragma unroll
    for (int it = 0; it < 8; it++) {
        int idx = tid + it * 256;
        int n = idx >> 4, cm = idx & 15;
        uint4 vh = *(uint4*)(smem + n * TST + cm * 16);
        uint4 vl = *(uint4*)(smem + 128 * TST + n * TST + cm * 16);
        size_t g = (size_t)(col0 + n) * NN + row0 + cm * 8;
        *(uint4*)(ThiOut + g) = vh;
        *(uint4*)(TloOut + g) = vl;
    }
}

// ======================= fused softmax + P@Wh GEMM ========================
// 512 threads (16 warps), tile M=64 x N=256, K=8192 in 256 chunks of 32.
// A = p (fp16, max-subtracted so p<=1), B = WhT fp16 hi/lo -> 2 MMA passes.
static constexpr int FB_STG    = 40960;                      // B stage hi+lo
static constexpr int F_OFF_ADJ = 3 * FB_STG;                 // 122880
static constexpr int F_ADJ_STG = 64 * 144;                   // 9216
static constexpr int F_OFF_A   = F_OFF_ADJ + 4 * F_ADJ_STG;  // 159744
static constexpr int F_OFF_RS  = F_OFF_A + 64 * 80;          // 164864
static constexpr int SMEM2_SZ  = F_OFF_RS + 256;             // 165120

__global__ void __launch_bounds__(512, 1) fused_gemm2(
    const int* __restrict__ adj, float* __restrict__ out)
{
    extern __shared__ char smem[];
    const uint32_t sb = smem_u32(smem);
    const int tid  = threadIdx.x;
    const int warp = tid >> 5;
    const int lane = tid & 31;
    const int wm   = warp & 1;           // 2 row-groups of 32 rows
    const int wn   = warp >> 1;          // 8 col-groups of 32 cols
    const int row0 = blockIdx.x * 64;

    const int a_row = lane & 15;
    const int a_kb  = (lane >> 4) * 16;
    const int b_row = ((lane >> 4) << 3) + (lane & 7);
    const int b_kb  = ((lane >> 3) & 1) * 16;

    const int r_loc = tid >> 3;          // 0..63 : row this thread handles
    const int kq    = tid & 7;           // 4-k slice within chunk

    auto load_B = [&](int slot, int c) {
        const uint32_t bb = sb + slot * FB_STG;
        const int k0 = c * 32;
        #pragma unroll
        for (int it = 0; it < 2; it++) {
            int n = (tid >> 2) + it * 128;
            uint32_t off = n * 80 + (tid & 3) * 16;
            size_t g = (size_t)n * NN + k0 + (tid & 3) * 8;
            cp_async16(bb + off,         g_WhThi + g);
            cp_async16(bb + 20480 + off, g_WhTlo + g);
        }
    };
    auto load_adj = [&](int slot, int c) {
        const uint32_t ab = sb + F_OFF_ADJ + slot * F_ADJ_STG;
        cp_async16(ab + r_loc * 144 + kq * 16,
                   adj + (size_t)(row0 + r_loc) * NN + c * 32 + kq * 4);
    };

    // row constants: C_r = leaky(f1_r + max(f2)) >= row max of leaky(f1+f2);
    // theta*cv is a per-row additive constant -> cancels in softmax, dropped.
    const float f1r = g_f1[row0 + r_loc];
    const float t0  = f1r + g_f2max;
    const float Cr  = t0 > 0.f ? t0 : ALPHA_S * t0;
    float psum = 0.f;

    float acc[2][4][4];
    #pragma unroll
    for (int i = 0; i < 2; i++)
        #pragma unroll
        for (int j = 0; j < 4; j++)
            #pragma unroll
            for (int q = 0; q < 4; q++) acc[i][j][q] = 0.0f;

    // prologue groups: G-2 {B0, adj0, adj1}, G-1 {B1, adj2}
    load_B(0, 0); load_adj(0, 0); load_adj(1, 1); cp_commit();
    load_B(1, 1); load_adj(2, 2); cp_commit();

    int br = 0, bw = 2, ar = 0, aw = 3;
    for (int c = 0; c < 256; c++) {
        if (c + 2 < 256) load_B(bw, c + 2);
        if (c + 3 < 256) load_adj(aw, c + 3);
        cp_commit();
        cp_wait<2>();

        // ---- compute p chunk -> A smem (fp16) ----
        {
            const char* ap = smem + F_OFF_ADJ + ar * F_ADJ_STG + r_loc * 144 + kq * 16;
            int4 av = *(const int4*)ap;
            float4 f2v = *(const float4*)(g_f2 + c * 32 + kq * 4);
            float e0 = f1r + f2v.x; e0 = e0 > 0.f ? e0 : ALPHA_S * e0;
            float e1 = f1r + f2v.y; e1 = e1 > 0.f ? e1 : ALPHA_S * e1;
            float e2 = f1r + f2v.z; e2 = e2 > 0.f ? e2 : ALPHA_S * e2;
            float e3 = f1r + f2v.w; e3 = e3 > 0.f ? e3 : ALPHA_S * e3;
            float p0 = av.x > 0 ? __expf(e0 - Cr) : 0.f;
            float p1 = av.y > 0 ? __expf(e1 - Cr) : 0.f;
            float p2 = av.z > 0 ? __expf(e2 - Cr) : 0.f;
            float p3 = av.w > 0 ? __expf(e3 - Cr) : 0.f;
            psum += (p0 + p1) + (p2 + p3);
            __half2 h01 = __floats2half2_rn(p0, p1);
            __half2 h23 = __floats2half2_rn(p2, p3);
            uint2 w;
            w.x = *(uint32_t*)&h01;
            w.y = *(uint32_t*)&h23;
            *(uint2*)(smem + F_OFF_A + r_loc * 80 + kq * 8) = w;
        }
        __syncthreads();

        // ---- MMA on chunk c ----
        const uint32_t bbase = sb + br * FB_STG;
        #pragma unroll
        for (int ks = 0; ks < 2; ks++) {
            const int kb = ks * 32;
            uint32_t af[2][4], bh[8], bl[8];
            #pragma unroll
            for (int mt = 0; mt < 2; mt++) {
                uint32_t ra = sb + F_OFF_A + (wm * 32 + mt * 16 + a_row) * 80 + kb + a_kb;
                ldm_x4(ra, af[mt][0], af[mt][1], af[mt][2], af[mt][3]);
            }
            #pragma unroll
            for (int nb = 0; nb < 2; nb++) {
                uint32_t rb = bbase + (wn * 32 + nb * 16 + b_row) * 80 + kb + b_kb;
                ldm_x4(rb,         bh[4*nb], bh[4*nb+1], bh[4*nb+2], bh[4*nb+3]);
                ldm_x4(rb + 20480, bl[4*nb], bl[4*nb+1], bl[4*nb+2], bl[4*nb+3]);
            }
            #pragma unroll
            for (int mt = 0; mt < 2; mt++)
                #pragma unroll
                for (int nt = 0; nt < 4; nt++) {
                    mma_fp16(acc[mt][nt], af[mt], bh + 2*nt);
                    mma_fp16(acc[mt][nt], af[mt], bl + 2*nt);
                }
        }
        __syncthreads();

        br = br == 2 ? 0 : br + 1;  bw = bw == 2 ? 0 : bw + 1;
        ar = ar == 3 ? 0 : ar + 1;  aw = aw == 3 ? 0 : aw + 1;
    }

    // ---- rowsum reduce (8 threads per row, consecutive lanes) ----
    psum += __shfl_xor_sync(0xffffffffu, psum, 1);
    psum += __shfl_xor_sync(0xffffffffu, psum, 2);
    psum += __shfl_xor_sync(0xffffffffu, psum, 4);
    if (kq == 0) *(float*)(smem + F_OFF_RS + r_loc * 4) = psum;
    __syncthreads();
    const float* rs = (const float*)(smem + F_OFF_RS);

    // ---- epilogue: out = elu(acc / rowsum) ----
    #pragma unroll
    for (int mt = 0; mt < 2; mt++) {
        int rAl = wm * 32 + mt * 16 + (lane >> 2);
        int rBl = rAl + 8;
        float invA = 1.0f / rs[rAl];
        float invB = 1.0f / rs[rBl];
        #pragma unroll
        for (int nt = 0; nt < 4; nt++) {
            int cc = wn * 32 + nt * 8 + (lane & 3) * 2;
            float v0 = acc[mt][nt][0] * invA;
            float v1 = acc[mt][nt][1] * invA;
            float v2 = acc[mt][nt][2] * invB;
            float v3 = acc[mt][nt][3] * invB;
            float2 oA = { v0 > 0.f ? v0 : expm1f(v0), v1 > 0.f ? v1 : expm1f(v1) };
            float2 oB = { v2 > 0.f ? v2 : expm1f(v2), v3 > 0.f ? v3 : expm1f(v3) };
            *(float2*)(out + (size_t)(row0 + rAl) * FD + cc) = oA;
            *(float2*)(out + (size_t)(row0 + rBl) * FD + cc) = oB;
        }
    }
}

// ---------------- input conversion ----------------
__global__ void convert_kernel(const float* __restrict__ h, const float* __restrict__ W)
{
    int t = blockIdx.x * 256 + threadIdx.x;
    if (blockIdx.x < NN) {
        float v = h[t];
        __nv_bfloat16 hb = __float2bfloat16(v);
        g_hhi[t] = hb;
        g_hlo[t] = __float2bfloat16(v - __bfloat162float(hb));
    } else {
        int idx = t - NN * 256;
        int o = idx >> 8, i = idx & 255;
        float v = W[i * FD + o];
        __nv_bfloat16 hb = __float2bfloat16(v);
        g_WThi[idx] = hb;
        g_WTlo[idx] = __float2bfloat16(v - __bfloat162float(hb));
    }
}

// ---------------- f1/f2 from WhT splits ----------------
__global__ void f1f2_kernel(const float* __restrict__ a)
{
    int m = blockIdx.x * 256 + threadIdx.x;
    float s1 = 0.0f, s2 = 0.0f;
    #pragma unroll 4
    for (int n = 0; n < FD; n++) {
        float v = __half2float(g_WhThi[(size_t)n * NN + m]) +
                  __half2float(g_WhTlo[(size_t)n * NN + m]);
        s1 = fmaf(v, __ldg(a + n),      s1);
        s2 = fmaf(v, __ldg(a + FD + n), s2);
    }
    g_f1[m] = s1;
    g_f2[m] = s2;
}

// ---------------- global max of f2 ----------------
__global__ void f2max_kernel()
{
    __shared__ float red[256];
    int tid = threadIdx.x;
    float m = -1e30f;
    for (int i = tid; i < NN; i += 256) m = fmaxf(m, g_f2[i]);
    red[tid] = m; __syncthreads();
    #pragma unroll
    for (int s = 128; s > 0; s >>= 1) {
        if (tid < s) red[tid] = fmaxf(red[tid], red[tid + s]);
        __syncthreads();
    }
    if (tid == 0) g_f2max = red[0];
}

// ---------------- launch ----------------
extern "C" void kernel_launch(void* const* d_in, const int* in_sizes, int n_in,
                              void* d_out, int out_size)
{
    const float* h   = (const float*)d_in[0];
    const int*   adj = (const int*)  d_in[1];
    const float* W   = (const float*)d_in[3];
    const float* a   = (const float*)d_in[4];
    float* out = (float*)d_out;

    __nv_bfloat16 *phhi, *phlo, *pWThi, *pWTlo;
    __half *pWhThi, *pWhTlo;
    cudaGetSymbolAddress((void**)&phhi,   g_hhi);
    cudaGetSymbolAddress((void**)&phlo,   g_hlo);
    cudaGetSymbolAddress((void**)&pWThi,  g_WThi);
    cudaGetSymbolAddress((void**)&pWTlo,  g_WTlo);
    cudaGetSymbolAddress((void**)&pWhThi, g_WhThi);
    cudaGetSymbolAddress((void**)&pWhTlo, g_WhTlo);

    cudaFuncSetAttribute(mma_gemm1<8>, cudaFuncAttributeMaxDynamicSharedMemorySize, SMEM1_SZ);
    cudaFuncSetAttribute(fused_gemm2,  cudaFuncAttributeMaxDynamicSharedMemorySize, SMEM2_SZ);

    // 1) bf16 hi/lo splits of h and W^T
    convert_kernel<<<NN + FD, 256>>>(h, W);

    // 2) Wh = h@W (bf16 3-pass); epilogue writes WhT fp16 hi/lo
    {
        dim3 grid(NN / 128, FD / 128);
        mma_gemm1<8><<<grid, 256, SMEM1_SZ>>>(
            phhi, phlo, pWThi, pWTlo, pWhThi, pWhTlo);
    }

    // 3) f1/f2 and global f2 max
    f1f2_kernel<<<NN / 256, 256>>>(a);
    f2max_kernel<<<1, 256>>>();

    // 4) fused masked-softmax + (P @ Wh)/rowsum + ELU
    fused_gemm2<<<NN / 64, 512, SMEM2_SZ>>>(adj, out);
}

// round 6
// speedup vs baseline: 1.2976x; 1.2976x over previous
#include <cuda_runtime.h>
#include <cuda_bf16.h>
#include <cuda_fp16.h>
#include <cstdint>
#include <math.h>

#define NN 8192
#define FD 256
#define ALPHA_S 0.2f

// ---------------- device global scratch ----------------
__device__ __nv_bfloat16 g_hhi[NN * FD];
__device__ __nv_bfloat16 g_hlo[NN * FD];
__device__ __nv_bfloat16 g_WThi[FD * FD];
__device__ __nv_bfloat16 g_WTlo[FD * FD];
__device__ __half g_WhThi[FD * NN];   // Wh^T [n][k] fp16 hi/lo
__device__ __half g_WhTlo[FD * NN];
__device__ float g_f1[NN];
__device__ float g_f2[NN];
__device__ unsigned int g_f2max_bits;

// monotonic float<->uint encoding for atomicMax
__device__ __forceinline__ unsigned int fkey(float f) {
    unsigned int b = __float_as_uint(f);
    return (b & 0x80000000u) ? ~b : (b | 0x80000000u);
}
__device__ __forceinline__ float fdec(unsigned int k) {
    unsigned int b = (k & 0x80000000u) ? (k & 0x7fffffffu) : ~k;
    return __uint_as_float(b);
}

// ---------------- PTX helpers ----------------
__device__ __forceinline__ uint32_t smem_u32(const void* p) {
    uint32_t a;
    asm("{ .reg .u64 t; cvta.to.shared.u64 t, %1; cvt.u32.u64 %0, t; }"
        : "=r"(a) : "l"(p));
    return a;
}
__device__ __forceinline__ void cp_async16(uint32_t dst, const void* src) {
    asm volatile("cp.async.cg.shared.global [%0], [%1], 16;"
                 :: "r"(dst), "l"(src) : "memory");
}
__device__ __forceinline__ void cp_commit() {
    asm volatile("cp.async.commit_group;" ::: "memory");
}
template<int N>
__device__ __forceinline__ void cp_wait() {
    asm volatile("cp.async.wait_group %0;" :: "n"(N) : "memory");
}
__device__ __forceinline__ void ldm_x4(uint32_t addr, uint32_t& r0, uint32_t& r1,
                                       uint32_t& r2, uint32_t& r3) {
    asm volatile("ldmatrix.sync.aligned.m8n8.x4.shared.b16 {%0,%1,%2,%3}, [%4];"
                 : "=r"(r0), "=r"(r1), "=r"(r2), "=r"(r3) : "r"(addr));
}
__device__ __forceinline__ void mma_bf16(float* c, const uint32_t* a, const uint32_t* b) {
    asm volatile(
        "mma.sync.aligned.m16n8k16.row.col.f32.bf16.bf16.f32 "
        "{%0,%1,%2,%3}, {%4,%5,%6,%7}, {%8,%9}, {%0,%1,%2,%3};"
        : "+f"(c[0]), "+f"(c[1]), "+f"(c[2]), "+f"(c[3])
        : "r"(a[0]), "r"(a[1]), "r"(a[2]), "r"(a[3]), "r"(b[0]), "r"(b[1]));
}
__device__ __forceinline__ void mma_fp16(float* c, const uint32_t* a, const uint32_t* b) {
    asm volatile(
        "mma.sync.aligned.m16n8k16.row.col.f32.f16.f16.f32 "
        "{%0,%1,%2,%3}, {%4,%5,%6,%7}, {%8,%9}, {%0,%1,%2,%3};"
        : "+f"(c[0]), "+f"(c[1]), "+f"(c[2]), "+f"(c[3])
        : "r"(a[0]), "r"(a[1]), "r"(a[2]), "r"(a[3]), "r"(b[0]), "r"(b[1]));
}

// ======================= GEMM1: Wh = h @ W (bf16 3-pass) ====
static constexpr int ROWB    = 80;
static constexpr int TILE_B  = 128 * ROWB;
static constexpr int STAGE_B = 4 * TILE_B;
static constexpr int SMEM1_SZ = 2 * STAGE_B;      // 81920

template<int KCHUNKS>
__global__ void __launch_bounds__(256, 1) mma_gemm1(
    const __nv_bfloat16* __restrict__ Ahi, const __nv_bfloat16* __restrict__ Alo,
    const __nv_bfloat16* __restrict__ Bhi, const __nv_bfloat16* __restrict__ Blo,
    __half* __restrict__ ThiOut, __half* __restrict__ TloOut)
{
    constexpr int K = KCHUNKS * 32;
    extern __shared__ char smem[];
    const uint32_t sb = smem_u32(smem);

    const int tid  = threadIdx.x;
    const int warp = tid >> 5;
    const int lane = tid & 31;
    const int wm   = warp & 3;
    const int wn   = warp >> 2;
    const int row0 = blockIdx.x * 128;
    const int col0 = blockIdx.y * 128;

    const int a_row = lane & 15;
    const int a_kb  = (lane >> 4) * 16;
    const int b_row = ((lane >> 4) << 3) + (lane & 7);
    const int b_kb  = ((lane >> 3) & 1) * 16;
    const int lrow = tid >> 2;
    const int lch  = tid & 3;

    float acc[2][8][4];
    #pragma unroll
    for (int i = 0; i < 2; i++)
        #pragma unroll
        for (int j = 0; j < 8; j++)
            #pragma unroll
            for (int q = 0; q < 4; q++) acc[i][j][q] = 0.0f;

    auto load_stage = [&](int s, int kc) {
        const uint32_t base = sb + s * STAGE_B;
        const int k0 = kc * 32;
        #pragma unroll
        for (int it = 0; it < 2; it++) {
            int r = lrow + it * 64;
            uint32_t doff = r * ROWB + lch * 16;
            size_t ga = (size_t)(row0 + r) * K + k0 + lch * 8;
            size_t gb = (size_t)(col0 + r) * K + k0 + lch * 8;
            cp_async16(base + 0 * TILE_B + doff, Ahi + ga);
            cp_async16(base + 1 * TILE_B + doff, Alo + ga);
            cp_async16(base + 2 * TILE_B + doff, Bhi + gb);
            cp_async16(base + 3 * TILE_B + doff, Blo + gb);
        }
        cp_commit();
    };

    load_stage(0, 0);

    for (int c = 0; c < KCHUNKS; c++) {
        const int s = c & 1;
        if (c + 1 < KCHUNKS) { load_stage(s ^ 1, c + 1); cp_wait<1>(); }
        else                 { cp_wait<0>(); }
        __syncthreads();

        const uint32_t base = sb + s * STAGE_B;
        #pragma unroll
        for (int ks = 0; ks < 2; ks++) {
            const int kb = ks * 32;
            uint32_t ah[2][4], al[2][4], bh[16], bl[16];
            #pragma unroll
            for (int mt = 0; mt < 2; mt++) {
                uint32_t ra = (wm * 32 + mt * 16 + a_row) * ROWB + kb + a_kb;
                ldm_x4(base + 0 * TILE_B + ra, ah[mt][0], ah[mt][1], ah[mt][2], ah[mt][3]);
                ldm_x4(base + 1 * TILE_B + ra, al[mt][0], al[mt][1], al[mt][2], al[mt][3]);
            }
            #pragma unroll
            for (int nb = 0; nb < 4; nb++) {
                uint32_t rb = (wn * 64 + nb * 16 + b_row) * ROWB + kb + b_kb;
                ldm_x4(base + 2 * TILE_B + rb, bh[4*nb], bh[4*nb+1], bh[4*nb+2], bh[4*nb+3]);
                ldm_x4(base + 3 * TILE_B + rb, bl[4*nb], bl[4*nb+1], bl[4*nb+2], bl[4*nb+3]);
            }
            #pragma unroll
            for (int mt = 0; mt < 2; mt++)
                #pragma unroll
                for (int nt = 0; nt < 8; nt++) {
                    mma_bf16(acc[mt][nt], ah[mt], bh + 2*nt);
                    mma_bf16(acc[mt][nt], ah[mt], bl + 2*nt);
                    mma_bf16(acc[mt][nt], al[mt], bh + 2*nt);
                }
        }
        __syncthreads();
    }

    // stage C^T fp16 hi/lo through smem, then coalesced store to [n][m]
    constexpr int TST = 272;
    __half* shT = (__half*)smem;
    __half* slT = (__half*)(smem + 128 * TST);
    #pragma unroll
    for (int mt = 0; mt < 2; mt++) {
        #pragma unroll
        for (int nt = 0; nt < 8; nt++) {
            int ml = wm * 32 + mt * 16 + (lane >> 2);
            int nl = wn * 64 + nt * 8 + (lane & 3) * 2;
            #pragma unroll
            for (int q = 0; q < 4; q++) {
                int m = ml + (q >> 1) * 8;
                int n = nl + (q & 1);
                float v = acc[mt][nt][q];
                __half hb = __float2half_rn(v);
                __half lb = __float2half_rn(v - __half2float(hb));
                shT[n * 136 + m] = hb;
                slT[n * 136 + m] = lb;
            }
        }
    }
    __syncthreads();
    #pragma unroll
    for (int it = 0; it < 8; it++) {
        int idx = tid + it * 256;
        int n = idx >> 4, cm = idx & 15;
        uint4 vh = *(uint4*)(smem + n * TST + cm * 16);
        uint4 vl = *(uint4*)(smem + 128 * TST + n * TST + cm * 16);
        size_t g = (size_t)(col0 + n) * NN + row0 + cm * 8;
        *(uint4*)(ThiOut + g) = vh;
        *(uint4*)(TloOut + g) = vl;
    }
}

// ======================= fused softmax + P@Wh GEMM ========================
// 512 threads (16 warps), tile M=64 x N=256, K=8192 in 256 chunks of 32.
// ONE sync per chunk: p[c+1] computed into triple-buffered A while MMA
// consumes A[c]; loads issued right after the barrier.
static constexpr int FB_STG    = 40960;                      // B stage hi+lo
static constexpr int F_OFF_ADJ = 3 * FB_STG;                 // 122880
static constexpr int F_ADJ_STG = 64 * 144;                   // 9216
static constexpr int F_OFF_A   = F_OFF_ADJ + 4 * F_ADJ_STG;  // 159744
static constexpr int F_A_STG   = 64 * 80;                    // 5120
static constexpr int F_OFF_RS  = F_OFF_A + 3 * F_A_STG;      // 175104
static constexpr int SMEM2_SZ  = F_OFF_RS + 256;             // 175360

__global__ void __launch_bounds__(512, 1) fused_gemm2(
    const int* __restrict__ adj, float* __restrict__ out)
{
    extern __shared__ char smem[];
    const uint32_t sb = smem_u32(smem);
    const int tid  = threadIdx.x;
    const int warp = tid >> 5;
    const int lane = tid & 31;
    const int wm   = warp & 1;           // 2 row-groups of 32 rows
    const int wn   = warp >> 1;          // 8 col-groups of 32 cols
    const int row0 = blockIdx.x * 64;

    const int a_row = lane & 15;
    const int a_kb  = (lane >> 4) * 16;
    const int b_row = ((lane >> 4) << 3) + (lane & 7);
    const int b_kb  = ((lane >> 3) & 1) * 16;

    const int r_loc = tid >> 3;          // 0..63 : row this thread handles
    const int kq    = tid & 7;           // 4-k slice within chunk

    auto load_B = [&](int slot, int c) {
        const uint32_t bb = sb + slot * FB_STG;
        const int k0 = c * 32;
        #pragma unroll
        for (int it = 0; it < 2; it++) {
            int n = (tid >> 2) + it * 128;
            uint32_t off = n * 80 + (tid & 3) * 16;
            size_t g = (size_t)n * NN + k0 + (tid & 3) * 8;
            cp_async16(bb + off,         g_WhThi + g);
            cp_async16(bb + 20480 + off, g_WhTlo + g);
        }
    };
    auto load_adj = [&](int slot, int c) {
        const uint32_t ab = sb + F_OFF_ADJ + slot * F_ADJ_STG;
        cp_async16(ab + r_loc * 144 + kq * 16,
                   adj + (size_t)(row0 + r_loc) * NN + c * 32 + kq * 4);
    };

    // row constants; theta*cv is row-constant -> cancels in softmax
    const float f2max = fdec(g_f2max_bits);
    const float f1r = g_f1[row0 + r_loc];
    const float t0  = f1r + f2max;
    const float Cr  = t0 > 0.f ? t0 : ALPHA_S * t0;
    float psum = 0.f;

    // compute p chunk c into A buffer abuf (reads ONLY this thread's adj bytes)
    auto compute_p = [&](int c, int aslot, int abuf) {
        const char* ap = smem + F_OFF_ADJ + aslot * F_ADJ_STG + r_loc * 144 + kq * 16;
        int4 av = *(const int4*)ap;
        float4 f2v = *(const float4*)(g_f2 + c * 32 + kq * 4);
        float e0 = f1r + f2v.x; e0 = e0 > 0.f ? e0 : ALPHA_S * e0;
        float e1 = f1r + f2v.y; e1 = e1 > 0.f ? e1 : ALPHA_S * e1;
        float e2 = f1r + f2v.z; e2 = e2 > 0.f ? e2 : ALPHA_S * e2;
        float e3 = f1r + f2v.w; e3 = e3 > 0.f ? e3 : ALPHA_S * e3;
        float p0 = av.x > 0 ? __expf(e0 - Cr) : 0.f;
        float p1 = av.y > 0 ? __expf(e1 - Cr) : 0.f;
        float p2 = av.z > 0 ? __expf(e2 - Cr) : 0.f;
        float p3 = av.w > 0 ? __expf(e3 - Cr) : 0.f;
        psum += (p0 + p1) + (p2 + p3);
        __half2 h01 = __floats2half2_rn(p0, p1);
        __half2 h23 = __floats2half2_rn(p2, p3);
        uint2 w;
        w.x = *(uint32_t*)&h01;
        w.y = *(uint32_t*)&h23;
        *(uint2*)(smem + F_OFF_A + abuf * F_A_STG + r_loc * 80 + kq * 8) = w;
    };

    float acc[2][4][4];
    #pragma unroll
    for (int i = 0; i < 2; i++)
        #pragma unroll
        for (int j = 0; j < 4; j++)
            #pragma unroll
            for (int q = 0; q < 4; q++) acc[i][j][q] = 0.0f;

    // prologue: groups G1{adj0}, G2{B0,adj1}, G3{B1,adj2}
    load_adj(0, 0);              cp_commit();
    load_B(0, 0); load_adj(1, 1); cp_commit();
    load_B(1, 1); load_adj(2, 2); cp_commit();
    cp_wait<2>();                        // G1 done: adj0
    compute_p(0, 0, 0);                  // p[0] -> A[0]

    int bR = 0, bW = 2, aR3 = 1, aW = 3, aBufW = 1;
    for (int c = 0; c < 256; c++) {
        // loop iter j commits group {B(j+2), adj(j+3)}; wait<1> here ensures
        // groups through {B(c), adj(c+1)} complete.
        cp_wait<1>();

        if (c + 1 < 256) compute_p(c + 1, aR3, aBufW);  // -> A[(c+1)%3]
        __syncthreads();   // A[c] visible to all; B slot (c+2)%3 free to refill

        if (c + 2 < 256) load_B(bW, c + 2);
        if (c + 3 < 256) load_adj(aW, c + 3);
        cp_commit();

        // ---- MMA on chunk c: A[(c)%3], B[(c)%3] ----
        const uint32_t bbase = sb + bR * FB_STG;
        const uint32_t abase = sb + F_OFF_A + (aBufW == 0 ? 2 : aBufW - 1) * F_A_STG;
        #pragma unroll
        for (int ks = 0; ks < 2; ks++) {
            const int kb = ks * 32;
            uint32_t af[2][4], bh[8], bl[8];
            #pragma unroll
            for (int mt = 0; mt < 2; mt++) {
                uint32_t ra = abase + (wm * 32 + mt * 16 + a_row) * 80 + kb + a_kb;
                ldm_x4(ra, af[mt][0], af[mt][1], af[mt][2], af[mt][3]);
            }
            #pragma unroll
            for (int nb = 0; nb < 2; nb++) {
                uint32_t rb = bbase + (wn * 32 + nb * 16 + b_row) * 80 + kb + b_kb;
                ldm_x4(rb,         bh[4*nb], bh[4*nb+1], bh[4*nb+2], bh[4*nb+3]);
                ldm_x4(rb + 20480, bl[4*nb], bl[4*nb+1], bl[4*nb+2], bl[4*nb+3]);
            }
            #pragma unroll
            for (int mt = 0; mt < 2; mt++)
                #pragma unroll
                for (int nt = 0; nt < 4; nt++) {
                    mma_fp16(acc[mt][nt], af[mt], bh + 2*nt);
                    mma_fp16(acc[mt][nt], af[mt], bl + 2*nt);
                }
        }

        bR = bR == 2 ? 0 : bR + 1;   bW = bW == 2 ? 0 : bW + 1;
        aR3 = aR3 == 3 ? 0 : aR3 + 1; aW = aW == 3 ? 0 : aW + 1;
        aBufW = aBufW == 2 ? 0 : aBufW + 1;
    }

    // ---- rowsum reduce (8 threads per row, consecutive lanes) ----
    psum += __shfl_xor_sync(0xffffffffu, psum, 1);
    psum += __shfl_xor_sync(0xffffffffu, psum, 2);
    psum += __shfl_xor_sync(0xffffffffu, psum, 4);
    __syncthreads();   // all MMA/ldm done before A region reuse below? (rs is separate; just order stores)
    if (kq == 0) *(float*)(smem + F_OFF_RS + r_loc * 4) = psum;
    __syncthreads();
    const float* rs = (const float*)(smem + F_OFF_RS);

    // ---- epilogue: out = elu(acc / rowsum) ----
    #pragma unroll
    for (int mt = 0; mt < 2; mt++) {
        int rAl = wm * 32 + mt * 16 + (lane >> 2);
        int rBl = rAl + 8;
        float invA = 1.0f / rs[rAl];
        float invB = 1.0f / rs[rBl];
        #pragma unroll
        for (int nt = 0; nt < 4; nt++) {
            int cc = wn * 32 + nt * 8 + (lane & 3) * 2;
            float v0 = acc[mt][nt][0] * invA;
            float v1 = acc[mt][nt][1] * invA;
            float v2 = acc[mt][nt][2] * invB;
            float v3 = acc[mt][nt][3] * invB;
            float2 oA = { v0 > 0.f ? v0 : expm1f(v0), v1 > 0.f ? v1 : expm1f(v1) };
            float2 oB = { v2 > 0.f ? v2 : expm1f(v2), v3 > 0.f ? v3 : expm1f(v3) };
            *(float2*)(out + (size_t)(row0 + rAl) * FD + cc) = oA;
            *(float2*)(out + (size_t)(row0 + rBl) * FD + cc) = oB;
        }
    }
}

// ---------------- input conversion ----------------
__global__ void convert_kernel(const float* __restrict__ h, const float* __restrict__ W)
{
    if (blockIdx.x == 0 && threadIdx.x == 0) g_f2max_bits = 0u;
    int t = blockIdx.x * 256 + threadIdx.x;
    if (blockIdx.x < NN) {
        float v = h[t];
        __nv_bfloat16 hb = __float2bfloat16(v);
        g_hhi[t] = hb;
        g_hlo[t] = __float2bfloat16(v - __bfloat162float(hb));
    } else {
        int idx = t - NN * 256;
        int o = idx >> 8, i = idx & 255;
        float v = W[i * FD + o];
        __nv_bfloat16 hb = __float2bfloat16(v);
        g_WThi[idx] = hb;
        g_WTlo[idx] = __float2bfloat16(v - __bfloat162float(hb));
    }
}

// ---------------- f1/f2 from WhT splits + global f2 max ----------------
__global__ void f1f2_kernel(const float* __restrict__ a)
{
    __shared__ float red[256];
    int tid = threadIdx.x;
    int m = blockIdx.x * 256 + tid;
    float s1 = 0.0f, s2 = 0.0f;
    #pragma unroll 4
    for (int n = 0; n < FD; n++) {
        float v = __half2float(g_WhThi[(size_t)n * NN + m]) +
                  __half2float(g_WhTlo[(size_t)n * NN + m]);
        s1 = fmaf(v, __ldg(a + n),      s1);
        s2 = fmaf(v, __ldg(a + FD + n), s2);
    }
    g_f1[m] = s1;
    g_f2[m] = s2;

    red[tid] = s2; __syncthreads();
    #pragma unroll
    for (int s = 128; s > 0; s >>= 1) {
        if (tid < s) red[tid] = fmaxf(red[tid], red[tid + s]);
        __syncthreads();
    }
    if (tid == 0) atomicMax(&g_f2max_bits, fkey(red[0]));
}

// ---------------- launch ----------------
extern "C" void kernel_launch(void* const* d_in, const int* in_sizes, int n_in,
                              void* d_out, int out_size)
{
    const float* h   = (const float*)d_in[0];
    const int*   adj = (const int*)  d_in[1];
    const float* W   = (const float*)d_in[3];
    const float* a   = (const float*)d_in[4];
    float* out = (float*)d_out;

    __nv_bfloat16 *phhi, *phlo, *pWThi, *pWTlo;
    __half *pWhThi, *pWhTlo;
    cudaGetSymbolAddress((void**)&phhi,   g_hhi);
    cudaGetSymbolAddress((void**)&phlo,   g_hlo);
    cudaGetSymbolAddress((void**)&pWThi,  g_WThi);
    cudaGetSymbolAddress((void**)&pWTlo,  g_WTlo);
    cudaGetSymbolAddress((void**)&pWhThi, g_WhThi);
    cudaGetSymbolAddress((void**)&pWhTlo, g_WhTlo);

    cudaFuncSetAttribute(mma_gemm1<8>, cudaFuncAttributeMaxDynamicSharedMemorySize, SMEM1_SZ);
    cudaFuncSetAttribute(fused_gemm2,  cudaFuncAttributeMaxDynamicSharedMemorySize, SMEM2_SZ);

    // 1) bf16 hi/lo splits of h and W^T (+ f2max init)
    convert_kernel<<<NN + FD, 256>>>(h, W);

    // 2) Wh = h@W (bf16 3-pass); epilogue writes WhT fp16 hi/lo
    {
        dim3 grid(NN / 128, FD / 128);
        mma_gemm1<8><<<grid, 256, SMEM1_SZ>>>(
            phhi, phlo, pWThi, pWTlo, pWhThi, pWhTlo);
    }

    // 3) f1/f2 + global f2 max
    f1f2_kernel<<<NN / 256, 256>>>(a);

    // 4) fused masked-softmax + (P @ Wh)/rowsum + ELU
    fused_gemm2<<<NN / 64, 512, SMEM2_SZ>>>(adj, out);
}

// round 7
// speedup vs baseline: 1.9072x; 1.4698x over previous
#include <cuda_runtime.h>
#include <cuda_bf16.h>
#include <cuda_fp16.h>
#include <cstdint>
#include <math.h>

#define NN 8192
#define FD 256
#define ALPHA_S 0.2f

// ---------------- device global scratch ----------------
__device__ __nv_bfloat16 g_hhi[NN * FD];
__device__ __nv_bfloat16 g_hlo[NN * FD];
__device__ __nv_bfloat16 g_WThi[FD * FD];
__device__ __nv_bfloat16 g_WTlo[FD * FD];
__device__ __half g_WhThi[FD * NN];   // Wh^T [n][k] fp16 hi/lo
__device__ __half g_WhTlo[FD * NN];
__device__ float g_f1[NN];
__device__ float g_f2[NN];
__device__ unsigned int g_f2max_bits;

__device__ __forceinline__ unsigned int fkey(float f) {
    unsigned int b = __float_as_uint(f);
    return (b & 0x80000000u) ? ~b : (b | 0x80000000u);
}
__device__ __forceinline__ float fdec(unsigned int k) {
    unsigned int b = (k & 0x80000000u) ? (k & 0x7fffffffu) : ~k;
    return __uint_as_float(b);
}

// ---------------- PTX helpers ----------------
__device__ __forceinline__ uint32_t smem_u32(const void* p) {
    uint32_t a;
    asm("{ .reg .u64 t; cvta.to.shared.u64 t, %1; cvt.u32.u64 %0, t; }"
        : "=r"(a) : "l"(p));
    return a;
}
__device__ __forceinline__ void cp_async16(uint32_t dst, const void* src) {
    asm volatile("cp.async.cg.shared.global [%0], [%1], 16;"
                 :: "r"(dst), "l"(src) : "memory");
}
__device__ __forceinline__ void cp_commit() {
    asm volatile("cp.async.commit_group;" ::: "memory");
}
template<int N>
__device__ __forceinline__ void cp_wait() {
    asm volatile("cp.async.wait_group %0;" :: "n"(N) : "memory");
}
__device__ __forceinline__ void ldm_x4(uint32_t addr, uint32_t& r0, uint32_t& r1,
                                       uint32_t& r2, uint32_t& r3) {
    asm volatile("ldmatrix.sync.aligned.m8n8.x4.shared.b16 {%0,%1,%2,%3}, [%4];"
                 : "=r"(r0), "=r"(r1), "=r"(r2), "=r"(r3) : "r"(addr));
}
__device__ __forceinline__ void mma_bf16(float* c, const uint32_t* a, const uint32_t* b) {
    asm volatile(
        "mma.sync.aligned.m16n8k16.row.col.f32.bf16.bf16.f32 "
        "{%0,%1,%2,%3}, {%4,%5,%6,%7}, {%8,%9}, {%0,%1,%2,%3};"
        : "+f"(c[0]), "+f"(c[1]), "+f"(c[2]), "+f"(c[3])
        : "r"(a[0]), "r"(a[1]), "r"(a[2]), "r"(a[3]), "r"(b[0]), "r"(b[1]));
}
__device__ __forceinline__ void mma_fp16(float* c, const uint32_t* a, const uint32_t* b) {
    asm volatile(
        "mma.sync.aligned.m16n8k16.row.col.f32.f16.f16.f32 "
        "{%0,%1,%2,%3}, {%4,%5,%6,%7}, {%8,%9}, {%0,%1,%2,%3};"
        : "+f"(c[0]), "+f"(c[1]), "+f"(c[2]), "+f"(c[3])
        : "r"(a[0]), "r"(a[1]), "r"(a[2]), "r"(a[3]), "r"(b[0]), "r"(b[1]));
}

// ======================= GEMM1: Wh = h @ W (bf16 3-pass) ====
static constexpr int ROWB    = 80;
static constexpr int TILE_B  = 128 * ROWB;
static constexpr int STAGE_B = 4 * TILE_B;
static constexpr int SMEM1_SZ = 2 * STAGE_B;      // 81920

template<int KCHUNKS>
__global__ void __launch_bounds__(256, 1) mma_gemm1(
    const __nv_bfloat16* __restrict__ Ahi, const __nv_bfloat16* __restrict__ Alo,
    const __nv_bfloat16* __restrict__ Bhi, const __nv_bfloat16* __restrict__ Blo,
    __half* __restrict__ ThiOut, __half* __restrict__ TloOut)
{
    constexpr int K = KCHUNKS * 32;
    extern __shared__ char smem[];
    const uint32_t sb = smem_u32(smem);

    const int tid  = threadIdx.x;
    const int warp = tid >> 5;
    const int lane = tid & 31;
    const int wm   = warp & 3;
    const int wn   = warp >> 2;
    const int row0 = blockIdx.x * 128;
    const int col0 = blockIdx.y * 128;

    const int a_row = lane & 15;
    const int a_kb  = (lane >> 4) * 16;
    const int b_row = ((lane >> 4) << 3) + (lane & 7);
    const int b_kb  = ((lane >> 3) & 1) * 16;
    const int lrow = tid >> 2;
    const int lch  = tid & 3;

    float acc[2][8][4];
    #pragma unroll
    for (int i = 0; i < 2; i++)
        #pragma unroll
        for (int j = 0; j < 8; j++)
            #pragma unroll
            for (int q = 0; q < 4; q++) acc[i][j][q] = 0.0f;

    auto load_stage = [&](int s, int kc) {
        const uint32_t base = sb + s * STAGE_B;
        const int k0 = kc * 32;
        #pragma unroll
        for (int it = 0; it < 2; it++) {
            int r = lrow + it * 64;
            uint32_t doff = r * ROWB + lch * 16;
            size_t ga = (size_t)(row0 + r) * K + k0 + lch * 8;
            size_t gb = (size_t)(col0 + r) * K + k0 + lch * 8;
            cp_async16(base + 0 * TILE_B + doff, Ahi + ga);
            cp_async16(base + 1 * TILE_B + doff, Alo + ga);
            cp_async16(base + 2 * TILE_B + doff, Bhi + gb);
            cp_async16(base + 3 * TILE_B + doff, Blo + gb);
        }
        cp_commit();
    };

    load_stage(0, 0);

    for (int c = 0; c < KCHUNKS; c++) {
        const int s = c & 1;
        if (c + 1 < KCHUNKS) { load_stage(s ^ 1, c + 1); cp_wait<1>(); }
        else                 { cp_wait<0>(); }
        __syncthreads();

        const uint32_t base = sb + s * STAGE_B;
        #pragma unroll
        for (int ks = 0; ks < 2; ks++) {
            const int kb = ks * 32;
            uint32_t ah[2][4], al[2][4], bh[16], bl[16];
            #pragma unroll
            for (int mt = 0; mt < 2; mt++) {
                uint32_t ra = (wm * 32 + mt * 16 + a_row) * ROWB + kb + a_kb;
                ldm_x4(base + 0 * TILE_B + ra, ah[mt][0], ah[mt][1], ah[mt][2], ah[mt][3]);
                ldm_x4(base + 1 * TILE_B + ra, al[mt][0], al[mt][1], al[mt][2], al[mt][3]);
            }
            #pragma unroll
            for (int nb = 0; nb < 4; nb++) {
                uint32_t rb = (wn * 64 + nb * 16 + b_row) * ROWB + kb + b_kb;
                ldm_x4(base + 2 * TILE_B + rb, bh[4*nb], bh[4*nb+1], bh[4*nb+2], bh[4*nb+3]);
                ldm_x4(base + 3 * TILE_B + rb, bl[4*nb], bl[4*nb+1], bl[4*nb+2], bl[4*nb+3]);
            }
            #pragma unroll
            for (int mt = 0; mt < 2; mt++)
                #pragma unroll
                for (int nt = 0; nt < 8; nt++) {
                    mma_bf16(acc[mt][nt], ah[mt], bh + 2*nt);
                    mma_bf16(acc[mt][nt], ah[mt], bl + 2*nt);
                    mma_bf16(acc[mt][nt], al[mt], bh + 2*nt);
                }
        }
        __syncthreads();
    }

    // stage C^T fp16 hi/lo through smem, then coalesced store to [n][m]
    constexpr int TST = 272;
    __half* shT = (__half*)smem;
    __half* slT = (__half*)(smem + 128 * TST);
    #pragma unroll
    for (int mt = 0; mt < 2; mt++) {
        #pragma unroll
        for (int nt = 0; nt < 8; nt++) {
            int ml = wm * 32 + mt * 16 + (lane >> 2);
            int nl = wn * 64 + nt * 8 + (lane & 3) * 2;
            #pragma unroll
            for (int q = 0; q < 4; q++) {
                int m = ml + (q >> 1) * 8;
                int n = nl + (q & 1);
                float v = acc[mt][nt][q];
                __half hb = __float2half_rn(v);
                __half lb = __float2half_rn(v - __half2float(hb));
                shT[n * 136 + m] = hb;
                slT[n * 136 + m] = lb;
            }
        }
    }
    __syncthreads();
    #pragma unroll
    for (int it = 0; it < 8; it++) {
        int idx = tid + it * 256;
        int n = idx >> 4, cm = idx & 15;
        uint4 vh = *(uint4*)(smem + n * TST + cm * 16);
        uint4 vl = *(uint4*)(smem + 128 * TST + n * TST + cm * 16);
        size_t g = (size_t)(col0 + n) * NN + row0 + cm * 8;
        *(uint4*)(ThiOut + g) = vh;
        *(uint4*)(TloOut + g) = vl;
    }
}

// ======================= fused softmax + P@Wh GEMM ========================
// 512 threads (16 warps), tile M=64 x N=256, K=8192 in 128 chunks of 64.
// A = p (fp16), B = WhT fp16 SINGLE pass (quantization noise averages out).
// ONE sync per chunk; p[c+1] overlapped against MMA[c]; triple-buffered.
static constexpr int FB_STG    = 256 * 144;                  // 36864
static constexpr int F_OFF_ADJ = 3 * FB_STG;                 // 110592
static constexpr int F_ADJ_STG = 64 * 272;                   // 17408
static constexpr int F_OFF_A   = F_OFF_ADJ + 3 * F_ADJ_STG;  // 162816
static constexpr int F_A_STG   = 64 * 144;                   // 9216
static constexpr int F_OFF_RS  = F_OFF_A + 3 * F_A_STG;      // 190464
static constexpr int SMEM2_SZ  = F_OFF_RS + 256;             // 190720

__global__ void __launch_bounds__(512, 1) fused_gemm2(
    const int* __restrict__ adj, float* __restrict__ out)
{
    extern __shared__ char smem[];
    const uint32_t sb = smem_u32(smem);
    const int tid  = threadIdx.x;
    const int warp = tid >> 5;
    const int lane = tid & 31;
    const int wm   = warp & 1;           // 2 row-groups of 32 rows
    const int wn   = warp >> 1;          // 8 col-groups of 32 cols
    const int row0 = blockIdx.x * 64;

    const int a_row = lane & 15;
    const int a_kb  = (lane >> 4) * 16;
    const int b_row = ((lane >> 4) << 3) + (lane & 7);
    const int b_kb  = ((lane >> 3) & 1) * 16;

    // p-compute mapping: thread owns rows rA=(tid>>4), rB=rA+32, cols [ch*4, +4)
    const int rA = tid >> 4;             // 0..31
    const int ch = tid & 15;

    auto load_B = [&](int slot, int c) {
        const uint32_t bb = sb + slot * FB_STG;
        const int k0 = c * 64;
        #pragma unroll
        for (int it = 0; it < 4; it++) {
            int idx = tid + it * 512;    // 0..2047
            int n = idx >> 3, c8 = idx & 7;
            cp_async16(bb + n * 144 + c8 * 16,
                       g_WhThi + (size_t)n * NN + k0 + c8 * 8);
        }
    };
    auto load_adj = [&](int slot, int c) {
        const uint32_t ab = sb + F_OFF_ADJ + slot * F_ADJ_STG;
        #pragma unroll
        for (int it = 0; it < 2; it++) {
            int idx = tid + it * 512;    // 0..1023
            int r = idx >> 4, cc = idx & 15;
            cp_async16(ab + r * 272 + cc * 16,
                       adj + (size_t)(row0 + r) * NN + c * 64 + cc * 4);
        }
    };

    // row constants; theta*cv and any per-row shift cancel in softmax
    const float f2max = fdec(g_f2max_bits);
    const float f1A = g_f1[row0 + rA];
    const float f1B = g_f1[row0 + rA + 32];
    float tA = f1A + f2max;  const float CrA = tA > 0.f ? tA : ALPHA_S * tA;
    float tB = f1B + f2max;  const float CrB = tB > 0.f ? tB : ALPHA_S * tB;
    float psumA = 0.f, psumB = 0.f;

    // compute p chunk c into A buffer abuf (reads ONLY this thread's adj bytes)
    auto compute_p = [&](int c, int aslot, int abuf) {
        const char* ab = smem + F_OFF_ADJ + aslot * F_ADJ_STG + ch * 16;
        int4 avA = *(const int4*)(ab + rA * 272);
        int4 avB = *(const int4*)(ab + (rA + 32) * 272);
        float4 f2v = *(const float4*)(g_f2 + c * 64 + ch * 4);
        float e0 = f2v.x, e1 = f2v.y, e2 = f2v.z, e3 = f2v.w;

        float a0 = f1A + e0; a0 = a0 > 0.f ? a0 : ALPHA_S * a0;
        float a1 = f1A + e1; a1 = a1 > 0.f ? a1 : ALPHA_S * a1;
        float a2 = f1A + e2; a2 = a2 > 0.f ? a2 : ALPHA_S * a2;
        float a3 = f1A + e3; a3 = a3 > 0.f ? a3 : ALPHA_S * a3;
        float pA0 = avA.x > 0 ? __expf(a0 - CrA) : 0.f;
        float pA1 = avA.y > 0 ? __expf(a1 - CrA) : 0.f;
        float pA2 = avA.z > 0 ? __expf(a2 - CrA) : 0.f;
        float pA3 = avA.w > 0 ? __expf(a3 - CrA) : 0.f;
        psumA += (pA0 + pA1) + (pA2 + pA3);

        float b0 = f1B + e0; b0 = b0 > 0.f ? b0 : ALPHA_S * b0;
        float b1 = f1B + e1; b1 = b1 > 0.f ? b1 : ALPHA_S * b1;
        float b2 = f1B + e2; b2 = b2 > 0.f ? b2 : ALPHA_S * b2;
        float b3 = f1B + e3; b3 = b3 > 0.f ? b3 : ALPHA_S * b3;
        float pB0 = avB.x > 0 ? __expf(b0 - CrB) : 0.f;
        float pB1 = avB.y > 0 ? __expf(b1 - CrB) : 0.f;
        float pB2 = avB.z > 0 ? __expf(b2 - CrB) : 0.f;
        float pB3 = avB.w > 0 ? __expf(b3 - CrB) : 0.f;
        psumB += (pB0 + pB1) + (pB2 + pB3);

        char* dst = smem + F_OFF_A + abuf * F_A_STG + ch * 8;
        __half2 hA01 = __floats2half2_rn(pA0, pA1);
        __half2 hA23 = __floats2half2_rn(pA2, pA3);
        uint2 wA; wA.x = *(uint32_t*)&hA01; wA.y = *(uint32_t*)&hA23;
        *(uint2*)(dst + rA * 144) = wA;
        __half2 hB01 = __floats2half2_rn(pB0, pB1);
        __half2 hB23 = __floats2half2_rn(pB2, pB3);
        uint2 wB; wB.x = *(uint32_t*)&hB01; wB.y = *(uint32_t*)&hB23;
        *(uint2*)(dst + (rA + 32) * 144) = wB;
    };

    float acc[2][4][4];
    #pragma unroll
    for (int i = 0; i < 2; i++)
        #pragma unroll
        for (int j = 0; j < 4; j++)
            #pragma unroll
            for (int q = 0; q < 4; q++) acc[i][j][q] = 0.0f;

    // prologue: groups G1{adj0}, G2{B0,adj1}, G3{B1,adj2}
    load_adj(0, 0);               cp_commit();
    load_B(0, 0); load_adj(1, 1); cp_commit();
    load_B(1, 1); load_adj(2, 2); cp_commit();
    cp_wait<2>();                        // adj0 ready
    compute_p(0, 0, 0);                  // p[0] -> A[0]

    int bR = 0, bW = 2, aR3 = 1, aW = 0, aBufW = 1;
    for (int c = 0; c < 128; c++) {
        // groups outstanding ensure B(c), adj(c+1) complete after wait<1>
        cp_wait<1>();

        if (c + 1 < 128) compute_p(c + 1, aR3, aBufW);
        __syncthreads();

        if (c + 2 < 128) load_B(bW, c + 2);
        if (c + 3 < 128) load_adj(aW, c + 3);
        cp_commit();

        // ---- MMA on chunk c ----
        const uint32_t bbase = sb + bR * FB_STG;
        const uint32_t abase = sb + F_OFF_A + (aBufW == 0 ? 2 : aBufW - 1) * F_A_STG;
        #pragma unroll
        for (int ks = 0; ks < 4; ks++) {
            const int kb = ks * 32;
            uint32_t af[2][4], bh[8];
            #pragma unroll
            for (int mt = 0; mt < 2; mt++) {
                uint32_t ra = abase + (wm * 32 + mt * 16 + a_row) * 144 + kb + a_kb;
                ldm_x4(ra, af[mt][0], af[mt][1], af[mt][2], af[mt][3]);
            }
            #pragma unroll
            for (int nb = 0; nb < 2; nb++) {
                uint32_t rb = bbase + (wn * 32 + nb * 16 + b_row) * 144 + kb + b_kb;
                ldm_x4(rb, bh[4*nb], bh[4*nb+1], bh[4*nb+2], bh[4*nb+3]);
            }
            #pragma unroll
            for (int mt = 0; mt < 2; mt++)
                #pragma unroll
                for (int nt = 0; nt < 4; nt++)
                    mma_fp16(acc[mt][nt], af[mt], bh + 2*nt);
        }

        bR = bR == 2 ? 0 : bR + 1;    bW = bW == 2 ? 0 : bW + 1;
        aR3 = aR3 == 2 ? 0 : aR3 + 1; aW = aW == 2 ? 0 : aW + 1;
        aBufW = aBufW == 2 ? 0 : aBufW + 1;
    }

    // ---- rowsum reduce (16 threads per row, xor within 16-lane half) ----
    #pragma unroll
    for (int o = 1; o < 16; o <<= 1) {
        psumA += __shfl_xor_sync(0xffffffffu, psumA, o);
        psumB += __shfl_xor_sync(0xffffffffu, psumB, o);
    }
    __syncthreads();
    if (ch == 0) {
        *(float*)(smem + F_OFF_RS + rA * 4)        = psumA;
        *(float*)(smem + F_OFF_RS + (rA + 32) * 4) = psumB;
    }
    __syncthreads();
    const float* rs = (const float*)(smem + F_OFF_RS);

    // ---- epilogue: out = elu(acc / rowsum) ----
    #pragma unroll
    for (int mt = 0; mt < 2; mt++) {
        int rAl = wm * 32 + mt * 16 + (lane >> 2);
        int rBl = rAl + 8;
        float invA = 1.0f / rs[rAl];
        float invB = 1.0f / rs[rBl];
        #pragma unroll
        for (int nt = 0; nt < 4; nt++) {
            int cc = wn * 32 + nt * 8 + (lane & 3) * 2;
            float v0 = acc[mt][nt][0] * invA;
            float v1 = acc[mt][nt][1] * invA;
            float v2 = acc[mt][nt][2] * invB;
            float v3 = acc[mt][nt][3] * invB;
            float2 oA = { v0 > 0.f ? v0 : expm1f(v0), v1 > 0.f ? v1 : expm1f(v1) };
            float2 oB = { v2 > 0.f ? v2 : expm1f(v2), v3 > 0.f ? v3 : expm1f(v3) };
            *(float2*)(out + (size_t)(row0 + rAl) * FD + cc) = oA;
            *(float2*)(out + (size_t)(row0 + rBl) * FD + cc) = oB;
        }
    }
}

// ---------------- input conversion ----------------
__global__ void convert_kernel(const float* __restrict__ h, const float* __restrict__ W)
{
    if (blockIdx.x == 0 && threadIdx.x == 0) g_f2max_bits = 0u;
    int t = blockIdx.x * 256 + threadIdx.x;
    if (blockIdx.x < NN) {
        float v = h[t];
        __nv_bfloat16 hb = __float2bfloat16(v);
        g_hhi[t] = hb;
        g_hlo[t] = __float2bfloat16(v - __bfloat162float(hb));
    } else {
        int idx = t - NN * 256;
        int o = idx >> 8, i = idx & 255;
        float v = W[i * FD + o];
        __nv_bfloat16 hb = __float2bfloat16(v);
        g_WThi[idx] = hb;
        g_WTlo[idx] = __float2bfloat16(v - __bfloat162float(hb));
    }
}

// ---------------- f1/f2 from WhT splits + global f2 max ----------------
__global__ void f1f2_kernel(const float* __restrict__ a)
{
    __shared__ float red[256];
    int tid = threadIdx.x;
    int m = blockIdx.x * 256 + tid;
    float s1 = 0.0f, s2 = 0.0f;
    #pragma unroll 4
    for (int n = 0; n < FD; n++) {
        float v = __half2float(g_WhThi[(size_t)n * NN + m]) +
                  __half2float(g_WhTlo[(size_t)n * NN + m]);
        s1 = fmaf(v, __ldg(a + n),      s1);
        s2 = fmaf(v, __ldg(a + FD + n), s2);
    }
    g_f1[m] = s1;
    g_f2[m] = s2;

    red[tid] = s2; __syncthreads();
    #pragma unroll
    for (int s = 128; s > 0; s >>= 1) {
        if (tid < s) red[tid] = fmaxf(red[tid], red[tid + s]);
        __syncthreads();
    }
    if (tid == 0) atomicMax(&g_f2max_bits, fkey(red[0]));
}

// ---------------- launch ----------------
extern "C" void kernel_launch(void* const* d_in, const int* in_sizes, int n_in,
                              void* d_out, int out_size)
{
    const float* h   = (const float*)d_in[0];
    const int*   adj = (const int*)  d_in[1];
    const float* W   = (const float*)d_in[3];
    const float* a   = (const float*)d_in[4];
    float* out = (float*)d_out;

    __nv_bfloat16 *phhi, *phlo, *pWThi, *pWTlo;
    __half *pWhThi, *pWhTlo;
    cudaGetSymbolAddress((void**)&phhi,   g_hhi);
    cudaGetSymbolAddress((void**)&phlo,   g_hlo);
    cudaGetSymbolAddress((void**)&pWThi,  g_WThi);
    cudaGetSymbolAddress((void**)&pWTlo,  g_WTlo);
    cudaGetSymbolAddress((void**)&pWhThi, g_WhThi);
    cudaGetSymbolAddress((void**)&pWhTlo, g_WhTlo);

    cudaFuncSetAttribute(mma_gemm1<8>, cudaFuncAttributeMaxDynamicSharedMemorySize, SMEM1_SZ);
    cudaFuncSetAttribute(fused_gemm2,  cudaFuncAttributeMaxDynamicSharedMemorySize, SMEM2_SZ);

    // 1) bf16 hi/lo splits of h and W^T (+ f2max init)
    convert_kernel<<<NN + FD, 256>>>(h, W);

    // 2) Wh = h@W (bf16 3-pass); epilogue writes WhT fp16 hi/lo
    {
        dim3 grid(NN / 128, FD / 128);
        mma_gemm1<8><<<grid, 256, SMEM1_SZ>>>(
            phhi, phlo, pWThi, pWTlo, pWhThi, pWhTlo);
    }

    // 3) f1/f2 (full precision hi+lo) + global f2 max
    f1f2_kernel<<<NN / 256, 256>>>(a);

    // 4) fused masked-softmax + (P @ Wh)/rowsum + ELU (single-pass fp16 B)
    fused_gemm2<<<NN / 64, 512, SMEM2_SZ>>>(adj, out);
}